// round 12
// baseline (speedup 1.0000x reference)
#include <cuda_runtime.h>
#include <cuda_fp16.h>
#include <cstdint>

#define BATCH 4
#define CKD   64
#define CVD   512
#define NMEM  9216
#define MQ    2304
#define NT    128
#define NTILES 72
#define MB    64          // m rows per CTA
#define THREADS 256

// half strides (conflict-free fragment loads: stride/2 ≡ 4 (mod 32) words)
#define SQK 72            // Qh/Kh rows: 64 halfs + pad
#define SPV 136           // Ph/Vh rows: 128 halfs + pad

// smem layout (float offsets)
#define OQH  0                     // Qh [64 m][72]   -> 2304 f
#define OKH  2304                  // Kh [128 n][72]  -> 4608 f
#define OPH  (OKH + 4608)          // Ph [64 m][136]  -> 4352 f
#define OVH  (OPH + 4352)          // Vh [128 cv][136]-> 8704 f
#define ORA  (OVH + 8704)          // row-sum partials [4][64]
#define OINV (ORA + 256)
#define SM_FLOATS (OINV + 64)
#define SMEM_BYTES (SM_FLOATS * 4) // 81,152 B -> 2 CTAs/SM

// ---------------------------------------------------------------------------
__device__ __forceinline__ uint32_t h2u(__half2 h) { return *(uint32_t*)&h; }

// m16n8k16 f16 mma, f32 accumulate.
__device__ __forceinline__ void mma16(float c[4], const uint32_t a[4],
                                      uint32_t b0, uint32_t b1) {
    asm volatile(
        "mma.sync.aligned.m16n8k16.row.col.f32.f16.f16.f32 "
        "{%0,%1,%2,%3}, {%4,%5,%6,%7}, {%8,%9}, {%0,%1,%2,%3};"
        : "+f"(c[0]), "+f"(c[1]), "+f"(c[2]), "+f"(c[3])
        : "r"(a[0]), "r"(a[1]), "r"(a[2]), "r"(a[3]), "r"(b0), "r"(b1));
}

// ---------------------------------------------------------------------------
__global__ __launch_bounds__(THREADS, 2)
void mr_kernel(const float* __restrict__ mk, const float* __restrict__ qk,
               const float* __restrict__ mv, float* __restrict__ out) {
    extern __shared__ float sm[];
    __half* Qh = (__half*)(sm + OQH);
    __half* Kh = (__half*)(sm + OKH);
    __half* Ph = (__half*)(sm + OPH);
    __half* Vh = (__half*)(sm + OVH);

    const int t = threadIdx.x, lane = t & 31, wid = t >> 5;
    const int g = lane >> 2, tig = lane & 3;
    const int wm1 = wid & 1, wn1 = wid >> 1;    // GEMM1: 2(m) x 4(n)
    const int wc2 = wid & 3, wm2 = wid >> 2;    // GEMM2: 4(cv) x 2(m)
    const int b = blockIdx.z;
    const int m0 = blockIdx.x * MB, cv0 = blockIdx.y * 128;

    const float* qb = qk + (size_t)b * CKD * MQ + m0;
    const float* kb = mk + (size_t)b * CKD * NMEM;
    const float* vb = mv + ((size_t)b * CVD + cv0) * NMEM;

    // ---- prologue: Q -> Qh[m][c] f16 (transpose via registers), once ----
    {
        const int mq_ = t & 63, cq = t >> 6;        // 4 c-quarters of 16
#pragma unroll 4
        for (int i = 0; i < 8; i++) {
            int c0 = cq * 16 + 2 * i;
            float x0 = qb[(size_t)c0 * MQ + mq_];
            float x1 = qb[(size_t)(c0 + 1) * MQ + mq_];
            *(__half2*)&Qh[mq_ * SQK + c0] = __floats2half2_rn(x0, x1);
        }
    }

    float oacc[2][4][4] = {};
    float rsum[4] = {0.f, 0.f, 0.f, 0.f};

    for (int tt = 0; tt < NTILES; tt++) {
        const int n0 = tt * NT;

        // ---- convert K: gmem [64c][128n] -> Kh[n][c] f16 (reg transpose) ----
        {
            const int nk = t & 127, ck = t >> 7;    // 2 c-halves of 32
            const float* kt = kb + n0 + nk;
#pragma unroll 4
            for (int i = 0; i < 16; i++) {
                int c0 = ck * 32 + 2 * i;
                float x0 = kt[(size_t)c0 * NMEM];
                float x1 = kt[(size_t)(c0 + 1) * NMEM];
                *(__half2*)&Kh[nk * SQK + c0] = __floats2half2_rn(x0, x1);
            }
        }
        // ---- convert V: gmem [128cv][128n] -> Vh[cv][n] f16 ----
        {
#pragma unroll 4
            for (int i = 0; i < 16; i++) {
                int idx = t + THREADS * i, cv = idx >> 5, q4 = (idx & 31) * 4;
                float4 x = *(const float4*)&vb[(size_t)cv * NMEM + n0 + q4];
                __half2 h0 = __floats2half2_rn(x.x, x.y);
                __half2 h1 = __floats2half2_rn(x.z, x.w);
                *(uint2*)&Vh[cv * SPV + q4] = make_uint2(h2u(h0), h2u(h1));
            }
        }
        __syncthreads();

        // ---- GEMM1: S[64m][128n] = Qh·Kh^T  (warp 32m x 32n, K=64) ----
        float sacc[2][4][4] = {};
        {
            const int mb = wm1 * 32, nb = wn1 * 32;
#pragma unroll
            for (int j = 0; j < 4; j++) {
                const int col = 16 * j + 2 * tig;
                uint32_t a[2][4];
#pragma unroll
                for (int i = 0; i < 2; i++) {
                    int r = mb + 16 * i + g;
                    a[i][0] = *(uint32_t*)&Qh[r * SQK + col];
                    a[i][1] = *(uint32_t*)&Qh[(r + 8) * SQK + col];
                    a[i][2] = *(uint32_t*)&Qh[r * SQK + col + 8];
                    a[i][3] = *(uint32_t*)&Qh[(r + 8) * SQK + col + 8];
                }
#pragma unroll
                for (int f = 0; f < 4; f++) {
                    int nr = nb + 8 * f + g;
                    uint32_t b0 = *(uint32_t*)&Kh[nr * SQK + col];
                    uint32_t b1 = *(uint32_t*)&Kh[nr * SQK + col + 8];
                    mma16(sacc[0][f], a[0], b0, b1);
                    mma16(sacc[1][f], a[1], b0, b1);
                }
            }
        }

        // ---- epilogue: exp -> Ph (f16), per-row partial sums ----
        {
            const int mb = wm1 * 32, nb = wn1 * 32;
            float ps[4] = {0.f, 0.f, 0.f, 0.f};
#pragma unroll
            for (int i = 0; i < 2; i++)
#pragma unroll
                for (int f = 0; f < 4; f++) {
                    float e0 = __expf(sacc[i][f][0] * 0.125f);
                    float e1 = __expf(sacc[i][f][1] * 0.125f);
                    float e2 = __expf(sacc[i][f][2] * 0.125f);
                    float e3 = __expf(sacc[i][f][3] * 0.125f);
                    ps[2 * i]     += e0 + e1;
                    ps[2 * i + 1] += e2 + e3;
                    int col = nb + 8 * f + 2 * tig;
                    int r = mb + 16 * i + g;
                    *(__half2*)&Ph[r * SPV + col] = __floats2half2_rn(e0, e1);
                    *(__half2*)&Ph[(r + 8) * SPV + col] = __floats2half2_rn(e2, e3);
                }
#pragma unroll
            for (int q = 0; q < 4; q++) {
                ps[q] += __shfl_xor_sync(0xffffffffu, ps[q], 1);
                ps[q] += __shfl_xor_sync(0xffffffffu, ps[q], 2);
                rsum[q] += ps[q];
            }
        }
        __syncthreads();           // Ph visible to all warps

        // ---- GEMM2: O^T[128cv][64m] += Vh·Ph^T  (warp 32cv x 32m, K=128) ----
        {
            const int cb = wc2 * 32, mb2 = wm2 * 32;
#pragma unroll 4
            for (int u = 0; u < 8; u++) {
                const int col = 16 * u + 2 * tig;
                uint32_t a[2][4];
#pragma unroll
                for (int i = 0; i < 2; i++) {
                    int r = cb + 16 * i + g;
                    a[i][0] = *(uint32_t*)&Vh[r * SPV + col];
                    a[i][1] = *(uint32_t*)&Vh[(r + 8) * SPV + col];
                    a[i][2] = *(uint32_t*)&Vh[r * SPV + col + 8];
                    a[i][3] = *(uint32_t*)&Vh[(r + 8) * SPV + col + 8];
                }
#pragma unroll
                for (int f = 0; f < 4; f++) {
                    int mr = mb2 + 8 * f + g;
                    uint32_t b0 = *(uint32_t*)&Ph[mr * SPV + col];
                    uint32_t b1 = *(uint32_t*)&Ph[mr * SPV + col + 8];
                    mma16(oacc[0][f], a[0], b0, b1);
                    mma16(oacc[1][f], a[1], b0, b1);
                }
            }
        }
        __syncthreads();           // Kh/Ph/Vh free for next tile
    }

    // ---- finalize: row sums -> inv, normalize + store O^T ----
    if (tig == 0) {
        float* rs = sm + ORA + wn1 * 64;
        const int mb = wm1 * 32;
        rs[mb + g]      = rsum[0];
        rs[mb + g + 8]  = rsum[1];
        rs[mb + g + 16] = rsum[2];
        rs[mb + g + 24] = rsum[3];
    }
    __syncthreads();
    if (t < 64)
        sm[OINV + t] = 1.0f / (sm[ORA + t] + sm[ORA + 64 + t] +
                               sm[ORA + 128 + t] + sm[ORA + 192 + t]);
    __syncthreads();

    {
        const int cb = wc2 * 32, mb2 = wm2 * 32;
#pragma unroll
        for (int i = 0; i < 2; i++)
#pragma unroll
            for (int f = 0; f < 4; f++) {
                int m_ = mb2 + 8 * f + 2 * tig;
                float iv0 = sm[OINV + m_], iv1 = sm[OINV + m_ + 1];
                int cv = cb + 16 * i + g;
                float* o0 = out + ((size_t)b * CVD + cv0 + cv) * MQ + m0 + m_;
                float* o1 = o0 + (size_t)8 * MQ;
                *(float2*)o0 = make_float2(oacc[i][f][0] * iv0, oacc[i][f][1] * iv1);
                *(float2*)o1 = make_float2(oacc[i][f][2] * iv0, oacc[i][f][3] * iv1);
            }
    }
}

// ---------------------------------------------------------------------------
extern "C" void kernel_launch(void* const* d_in, const int* in_sizes, int n_in,
                              void* d_out, int out_size) {
    const float* mk = (const float*)d_in[0];
    const float* qk = (const float*)d_in[1];
    const float* mv = (const float*)d_in[2];
    float* out = (float*)d_out;

    cudaFuncSetAttribute(mr_kernel, cudaFuncAttributeMaxDynamicSharedMemorySize,
                         SMEM_BYTES);
    dim3 grid(MQ / MB, CVD / 128, BATCH);    // 36 x 4 x 4 = 576 CTAs
    mr_kernel<<<grid, THREADS, SMEM_BYTES>>>(mk, qk, mv, out);
}

// round 13
// speedup vs baseline: 1.3974x; 1.3974x over previous
#include <cuda_runtime.h>
#include <cuda_fp16.h>
#include <cstdint>

#define BATCH 4
#define CKD   64
#define CVD   512
#define NMEM  9216
#define MQ    2304
#define NT    128
#define NTILES 72
#define THREADS 512

// half strides (conflict-free fragment loads)
#define SQK 72            // Qh/Kh rows: 64 halfs + pad
#define SPV 136           // Ph/Vh rows: 128 halfs + pad

// smem layout (float offsets)
#define OQH  0            // Qh  [128 m][72]  f16      4608 f
#define OKH0 4608         // Kh buf0 [128 n][72] f16   4608 f
#define OKH1 9216         // Kh buf1                   4608 f
#define OPH  13824        // Ph [128 m][136] f16       8704 f
#define OVH  22528        // Vh [128 cv][136] f16      8704 f
#define OKS0 31232        // K staging buf0 [64c][132] 8448 f
#define OKS1 39680        // K staging buf1            8448 f
#define ORA  48128        // row-sum partials [4][128]
#define OINV 48640
#define SM_FLOATS 48768
#define SMEM_BYTES (SM_FLOATS * 4)   // 195,072 B

// ---------------------------------------------------------------------------
__device__ __forceinline__ uint32_t s2u(const void* p) {
    uint32_t a;
    asm("{.reg .u64 t; cvta.to.shared.u64 t, %1; cvt.u32.u64 %0, t;}" : "=r"(a) : "l"(p));
    return a;
}
__device__ __forceinline__ void cpa16(uint32_t s, const void* g) {
    asm volatile("cp.async.cg.shared.global [%0], [%1], 16;" :: "r"(s), "l"(g));
}
#define CP_COMMIT() asm volatile("cp.async.commit_group;" ::: "memory")
#define CP_WAIT(N)  asm volatile("cp.async.wait_group %0;" :: "n"(N) : "memory")

__device__ __forceinline__ uint32_t h2u(__half2 h) { return *(uint32_t*)&h; }

// m16n8k16 f16 mma, f32 accumulate.
__device__ __forceinline__ void mma16(float c[4], const uint32_t a[4],
                                      uint32_t b0, uint32_t b1) {
    asm volatile(
        "mma.sync.aligned.m16n8k16.row.col.f32.f16.f16.f32 "
        "{%0,%1,%2,%3}, {%4,%5,%6,%7}, {%8,%9}, {%0,%1,%2,%3};"
        : "+f"(c[0]), "+f"(c[1]), "+f"(c[2]), "+f"(c[3])
        : "r"(a[0]), "r"(a[1]), "r"(a[2]), "r"(a[3]), "r"(b0), "r"(b1));
}

// ---------------------------------------------------------------------------
__global__ __launch_bounds__(THREADS, 1)
void mr_kernel(const float* __restrict__ mk, const float* __restrict__ qk,
               const float* __restrict__ mv, float* __restrict__ out) {
    extern __shared__ float sm[];
    __half* Qh = (__half*)(sm + OQH);
    __half* Ph = (__half*)(sm + OPH);
    __half* Vh = (__half*)(sm + OVH);

    const int t = threadIdx.x, lane = t & 31, wid = t >> 5;
    const int g = lane >> 2, tig = lane & 3;
    const int wm = wid & 3, wn = wid >> 2;          // 4 x 4 warp grid
    const int b = blockIdx.z;
    const int m0 = blockIdx.x * 128, cv0 = blockIdx.y * 128;

    const float* qb = qk + (size_t)b * CKD * MQ + m0;
    const float* kb = mk + (size_t)b * CKD * NMEM;
    const float* vb = mv + ((size_t)b * CVD + cv0) * NMEM;

    // ---- prologue: Q -> staging -> Qh (transpose + f16), once ----
#pragma unroll
    for (int i = 0; i < 4; i++) {
        int idx = t + THREADS * i, c = idx >> 5, q = (idx & 31) * 4;
        cpa16(s2u(sm + OKS0 + c * 132 + q), qb + (size_t)c * MQ + q);
    }
    CP_COMMIT(); CP_WAIT(0);
    __syncthreads();
    {
        const int m = t >> 2, t3 = t & 3;
#pragma unroll
        for (int i = 0; i < 8; i++) {
            int c0 = 2 * t3 + 8 * i;
            float x0 = sm[OKS0 + c0 * 132 + m];
            float x1 = sm[OKS0 + (c0 + 1) * 132 + m];
            *(__half2*)&Qh[m * SQK + c0] = __floats2half2_rn(x0, x1);
        }
    }
    __syncthreads();
    // stage K_0 (buf0) and K_1 (buf1)
#pragma unroll
    for (int i = 0; i < 4; i++) {
        int idx = t + THREADS * i, c = idx >> 5, q = (idx & 31) * 4;
        cpa16(s2u(sm + OKS0 + c * 132 + q), kb + (size_t)c * NMEM + q);
    }
    CP_COMMIT();
#pragma unroll
    for (int i = 0; i < 4; i++) {
        int idx = t + THREADS * i, c = idx >> 5, q = (idx & 31) * 4;
        cpa16(s2u(sm + OKS1 + c * 132 + q), kb + (size_t)(c * NMEM + NT) + q);
    }
    CP_COMMIT();
    CP_WAIT(1);                 // K_0 landed (K_1 still in flight)
    __syncthreads();
    {   // convert K_0 -> Kh buf0
        __half* Kh0 = (__half*)(sm + OKH0);
        const int n = t >> 2, t3 = t & 3;
#pragma unroll
        for (int i = 0; i < 8; i++) {
            int c0 = 2 * t3 + 8 * i;
            float x0 = sm[OKS0 + c0 * 132 + n];
            float x1 = sm[OKS0 + (c0 + 1) * 132 + n];
            *(__half2*)&Kh0[n * SQK + c0] = __floats2half2_rn(x0, x1);
        }
    }

    float oacc[2][4][4] = {};
    float rsum[4] = {0.f, 0.f, 0.f, 0.f};

    for (int tt = 0; tt < NTILES; tt++) {
        const int n0 = tt * NT;
        __half* KhC = (__half*)(sm + ((tt & 1) ? OKH1 : OKH0));
        __half* KhN = (__half*)(sm + ((tt & 1) ? OKH0 : OKH1));
        const float* KsN = sm + (((tt + 1) & 1) ? OKS1 : OKS0); // holds K_{tt+1}
        float* KsD = sm + ((tt & 1) ? OKS1 : OKS0);             // dest K_{tt+2}
        const bool hasN1 = (tt + 1 < NTILES), hasN2 = (tt + 2 < NTILES);

        __syncthreads();   // Vh/Ph/KhN free; KhC/ (Q) ready

        // ---- phase 1: GEMM1 (Qh·KhC^T) interleaved with V LDG->f16->Vh ----
        float sacc[2][4][4] = {};
        {
            const int mb = wm * 32, nb = wn * 32;
#pragma unroll
            for (int j = 0; j < 4; j++) {
                // V chunk loads (gmem, L2-resident) — issue early
                int idx0 = t + THREADS * (2 * j), idx1 = idx0 + THREADS;
                float4 v0 = *(const float4*)&vb[(size_t)(idx0 >> 5) * NMEM + n0 + (idx0 & 31) * 4];
                float4 v1 = *(const float4*)&vb[(size_t)(idx1 >> 5) * NMEM + n0 + (idx1 & 31) * 4];

                const int col = 16 * j + 2 * tig;
                uint32_t a[2][4];
#pragma unroll
                for (int i = 0; i < 2; i++) {
                    int r = mb + 16 * i + g;
                    a[i][0] = *(uint32_t*)&Qh[r * SQK + col];
                    a[i][1] = *(uint32_t*)&Qh[(r + 8) * SQK + col];
                    a[i][2] = *(uint32_t*)&Qh[r * SQK + col + 8];
                    a[i][3] = *(uint32_t*)&Qh[(r + 8) * SQK + col + 8];
                }
#pragma unroll
                for (int f = 0; f < 4; f++) {
                    int nr = nb + 8 * f + g;
                    uint32_t b0 = *(uint32_t*)&KhC[nr * SQK + col];
                    uint32_t b1 = *(uint32_t*)&KhC[nr * SQK + col + 8];
                    mma16(sacc[0][f], a[0], b0, b1);
                    mma16(sacc[1][f], a[1], b0, b1);
                }

                // convert + store V chunks
                __half2 h00 = __floats2half2_rn(v0.x, v0.y);
                __half2 h01 = __floats2half2_rn(v0.z, v0.w);
                *(uint2*)&Vh[(idx0 >> 5) * SPV + (idx0 & 31) * 4] =
                    make_uint2(h2u(h00), h2u(h01));
                __half2 h10 = __floats2half2_rn(v1.x, v1.y);
                __half2 h11 = __floats2half2_rn(v1.z, v1.w);
                *(uint2*)&Vh[(idx1 >> 5) * SPV + (idx1 & 31) * 4] =
                    make_uint2(h2u(h10), h2u(h11));
            }
        }

        // ---- epilogue: exp -> Ph (f16), per-row partial sums ----
        {
            const int mb = wm * 32, nb = wn * 32;
            float ps[4] = {0.f, 0.f, 0.f, 0.f};
#pragma unroll
            for (int i = 0; i < 2; i++)
#pragma unroll
                for (int f = 0; f < 4; f++) {
                    float e0 = __expf(sacc[i][f][0] * 0.125f);
                    float e1 = __expf(sacc[i][f][1] * 0.125f);
                    float e2 = __expf(sacc[i][f][2] * 0.125f);
                    float e3 = __expf(sacc[i][f][3] * 0.125f);
                    ps[2 * i]     += e0 + e1;
                    ps[2 * i + 1] += e2 + e3;
                    int col = nb + 8 * f + 2 * tig;
                    int r = mb + 16 * i + g;
                    *(__half2*)&Ph[r * SPV + col] = __floats2half2_rn(e0, e1);
                    *(__half2*)&Ph[(r + 8) * SPV + col] = __floats2half2_rn(e2, e3);
                }
#pragma unroll
            for (int q = 0; q < 4; q++) {
                ps[q] += __shfl_xor_sync(0xffffffffu, ps[q], 1);
                ps[q] += __shfl_xor_sync(0xffffffffu, ps[q], 2);
                rsum[q] += ps[q];
            }
        }

        if (hasN1) CP_WAIT(0);   // K_{tt+1} landed (before barrier: visibility)
        __syncthreads();         // Ph + Vh visible; staging ready

        // ---- phase 3: GEMM2 (Vh·Ph^T) interleaved with K-convert(tt+1) ----
        if (hasN2) {             // prefetch K_{tt+2}
            const float* kb2 = kb + (size_t)(tt + 2) * NT;
#pragma unroll
            for (int i = 0; i < 4; i++) {
                int idx = t + THREADS * i, c = idx >> 5, q = (idx & 31) * 4;
                cpa16(s2u(KsD + c * 132 + q), kb2 + (size_t)c * NMEM + q);
            }
            CP_COMMIT();
        }
        {
            const int cb = wm * 32, mb2 = wn * 32;
            const int nk = t >> 2, t3 = t & 3;
#pragma unroll
            for (int u = 0; u < 8; u++) {
                if (hasN1) {     // K-convert chunk u -> KhN
                    int c0 = 2 * t3 + 8 * u;
                    float x0 = KsN[c0 * 132 + nk];
                    float x1 = KsN[(c0 + 1) * 132 + nk];
                    *(__half2*)&KhN[nk * SQK + c0] = __floats2half2_rn(x0, x1);
                }
                const int col = 16 * u + 2 * tig;
                uint32_t a[2][4];
#pragma unroll
                for (int i = 0; i < 2; i++) {
                    int r = cb + 16 * i + g;
                    a[i][0] = *(uint32_t*)&Vh[r * SPV + col];
                    a[i][1] = *(uint32_t*)&Vh[(r + 8) * SPV + col];
                    a[i][2] = *(uint32_t*)&Vh[r * SPV + col + 8];
                    a[i][3] = *(uint32_t*)&Vh[(r + 8) * SPV + col + 8];
                }
#pragma unroll
                for (int f = 0; f < 4; f++) {
                    int mr = mb2 + 8 * f + g;
                    uint32_t b0 = *(uint32_t*)&Ph[mr * SPV + col];
                    uint32_t b1 = *(uint32_t*)&Ph[mr * SPV + col + 8];
                    mma16(oacc[0][f], a[0], b0, b1);
                    mma16(oacc[1][f], a[1], b0, b1);
                }
            }
        }
    }

    // ---- finalize: row sums -> inv, normalize + store O^T ----
    __syncthreads();
    if (tig == 0) {
        float* rs = sm + ORA + wn * 128;
        const int mb = wm * 32;
        rs[mb + g]      = rsum[0];
        rs[mb + g + 8]  = rsum[1];
        rs[mb + g + 16] = rsum[2];
        rs[mb + g + 24] = rsum[3];
    }
    __syncthreads();
    if (t < 128)
        sm[OINV + t] = 1.0f / (sm[ORA + t] + sm[ORA + 128 + t] +
                               sm[ORA + 256 + t] + sm[ORA + 384 + t]);
    __syncthreads();

    {
        const int cb = wm * 32, mb2 = wn * 32;
#pragma unroll
        for (int i = 0; i < 2; i++)
#pragma unroll
            for (int f = 0; f < 4; f++) {
                int m_ = mb2 + 8 * f + 2 * tig;
                float iv0 = sm[OINV + m_], iv1 = sm[OINV + m_ + 1];
                int cv = cb + 16 * i + g;
                float* o0 = out + ((size_t)b * CVD + cv0 + cv) * MQ + m0 + m_;
                float* o1 = o0 + (size_t)8 * MQ;
                *(float2*)o0 = make_float2(oacc[i][f][0] * iv0, oacc[i][f][1] * iv1);
                *(float2*)o1 = make_float2(oacc[i][f][2] * iv0, oacc[i][f][3] * iv1);
            }
    }
}

// ---------------------------------------------------------------------------
extern "C" void kernel_launch(void* const* d_in, const int* in_sizes, int n_in,
                              void* d_out, int out_size) {
    const float* mk = (const float*)d_in[0];
    const float* qk = (const float*)d_in[1];
    const float* mv = (const float*)d_in[2];
    float* out = (float*)d_out;

    cudaFuncSetAttribute(mr_kernel, cudaFuncAttributeMaxDynamicSharedMemorySize,
                         SMEM_BYTES);
    dim3 grid(MQ / 128, CVD / 128, BATCH);   // 18 x 4 x 4 = 288
    mr_kernel<<<grid, THREADS, SMEM_BYTES>>>(mk, qk, mv, out);
}